// round 1
// baseline (speedup 1.0000x reference)
#include <cuda_runtime.h>
#include <math.h>

#define FIELD 39
#define EMBD 8
#define MAXB 16384
#define D0 312
#define D1 512
#define D2 256
#define D3 128

// Scratch (allocation-free rule: __device__ globals)
__device__ float g_S[FIELD * FIELD];
__device__ float g_li[MAXB];
__device__ float g_h0[MAXB * D0];
__device__ float g_h1[MAXB * D1];
__device__ float g_h2[MAXB * D2];
__device__ float g_h3[MAXB * D3];

// ---------------------------------------------------------------------------
// 1. S matrix: constant 39x39, strictly upper triangular.
//    Vi[i][g][e] = FM_V[i, i*1000, g, e];  S[i][j] = sum_e Vi[i][j%8][e]*Vi[j][i%8][e]
// ---------------------------------------------------------------------------
__global__ void compute_S_kernel(const float* __restrict__ FM_V) {
    __shared__ float Vi[FIELD][8][EMBD];
    for (int idx = threadIdx.x; idx < FIELD * 64; idx += blockDim.x) {
        int i = idx / 64;
        int r = idx % 64;
        // offset = ((i*50000 + i*1000) * 8 + g) * 8 + e = i*51000*64 + r
        long long off = (long long)i * (51000LL * 64LL) + r;
        Vi[i][r >> 3][r & 7] = FM_V[off];
    }
    __syncthreads();
    for (int idx = threadIdx.x; idx < FIELD * FIELD; idx += blockDim.x) {
        int i = idx / FIELD, j = idx % FIELD;
        float s = 0.f;
        if (j > i) {
#pragma unroll
            for (int e = 0; e < EMBD; e++)
                s += Vi[i][j & 7][e] * Vi[j][i & 7][e];
        }
        g_S[idx] = s;
    }
}

// ---------------------------------------------------------------------------
// 2. linear + interaction per sample (one thread per sample)
// ---------------------------------------------------------------------------
__global__ __launch_bounds__(256) void linear_inter_kernel(
    const int* __restrict__ ids, const float* __restrict__ vals,
    const float* __restrict__ FM_W, const float* __restrict__ FM_B, int B)
{
    __shared__ float Ss[FIELD * FIELD];
    for (int idx = threadIdx.x; idx < FIELD * FIELD; idx += blockDim.x)
        Ss[idx] = g_S[idx];
    __syncthreads();

    int b = blockIdx.x * blockDim.x + threadIdx.x;
    if (b >= B) return;

    float v[FIELD];
    float lin = 0.f;
#pragma unroll
    for (int f = 0; f < FIELD; f++) {
        v[f] = vals[b * FIELD + f];
        lin += FM_W[ids[b * FIELD + f]] * v[f];
    }
    float inter = 0.f;
#pragma unroll
    for (int i = 0; i < FIELD; i++) {
        float ti = 0.f;
#pragma unroll
        for (int j = i + 1; j < FIELD; j++)
            ti += Ss[i * FIELD + j] * v[j];
        inter += v[i] * ti;
    }
    g_li[b] = lin + inter + FM_B[0];
}

// ---------------------------------------------------------------------------
// 3. embedding gather -> h0 (B x 312), thread per (b, field), float4 x2
// ---------------------------------------------------------------------------
__global__ void gather_kernel(const int* __restrict__ ids,
                              const float* __restrict__ emb, int B)
{
    int idx = blockIdx.x * blockDim.x + threadIdx.x;
    if (idx >= B * FIELD) return;
    int id = ids[idx];
    int b = idx / FIELD, f = idx % FIELD;
    const float4* e = (const float4*)(emb + (size_t)id * EMBD);
    float4* dst = (float4*)(g_h0 + (size_t)b * D0 + f * EMBD);
    float4 e0 = e[0];
    float4 e1 = e[1];
    dst[0] = e0;
    dst[1] = e1;
}

// ---------------------------------------------------------------------------
// 4. fp32 SGEMM + bias + ReLU.  C[M,N] = relu(A[M,K] @ W[K,N] + bias)
//    BM=BN=128, BK=8, 256 threads, 8x8 per-thread tile.
//    Requires M%128==0, N%128==0, K%8==0 (true for all layers).
// ---------------------------------------------------------------------------
__global__ __launch_bounds__(256) void gemm128_bias_relu(
    const float* __restrict__ A, const float* __restrict__ W,
    const float* __restrict__ bias, float* __restrict__ C,
    int M, int N, int K)
{
    __shared__ float As[8][128];
    __shared__ float Bs[8][128];

    const int t = threadIdx.x;
    const int bm = blockIdx.y * 128;
    const int bn = blockIdx.x * 128;
    const int tx = t & 15, ty = t >> 4;
    const int tm = ty * 8, tn = tx * 8;

    // load mappings (one float4 each per stage)
    const int arow = t >> 1, acol = (t & 1) * 4;   // A: 128 rows x 8 cols
    const int wrow = t >> 5, wcol = (t & 31) * 4;  // W: 8 rows x 128 cols

    float acc[8][8] = {};

    const float* Ap = A + (size_t)(bm + arow) * K + acol;
    for (int k0 = 0; k0 < K; k0 += 8) {
        float4 a = *(const float4*)(Ap + k0);
        As[acol + 0][arow] = a.x;
        As[acol + 1][arow] = a.y;
        As[acol + 2][arow] = a.z;
        As[acol + 3][arow] = a.w;
        float4 w = *(const float4*)(W + (size_t)(k0 + wrow) * N + bn + wcol);
        *(float4*)&Bs[wrow][wcol] = w;
        __syncthreads();

#pragma unroll
        for (int k = 0; k < 8; k++) {
            float ra[8], rb[8];
            *(float4*)&ra[0] = *(const float4*)&As[k][tm];
            *(float4*)&ra[4] = *(const float4*)&As[k][tm + 4];
            *(float4*)&rb[0] = *(const float4*)&Bs[k][tn];
            *(float4*)&rb[4] = *(const float4*)&Bs[k][tn + 4];
#pragma unroll
            for (int i = 0; i < 8; i++)
#pragma unroll
                for (int j = 0; j < 8; j++)
                    acc[i][j] += ra[i] * rb[j];
        }
        __syncthreads();
    }

    float bvals[8];
#pragma unroll
    for (int j = 0; j < 8; j++) bvals[j] = bias[bn + tn + j];

#pragma unroll
    for (int i = 0; i < 8; i++) {
        float* crow = C + (size_t)(bm + tm + i) * N + bn + tn;
#pragma unroll
        for (int j = 0; j < 8; j += 4) {
            float4 o;
            o.x = fmaxf(acc[i][j + 0] + bvals[j + 0], 0.f);
            o.y = fmaxf(acc[i][j + 1] + bvals[j + 1], 0.f);
            o.z = fmaxf(acc[i][j + 2] + bvals[j + 2], 0.f);
            o.w = fmaxf(acc[i][j + 3] + bvals[j + 3], 0.f);
            *(float4*)(crow + j) = o;
        }
    }
}

// ---------------------------------------------------------------------------
// 5. output head: warp per sample. dot(h3, outW) + outB + li -> sigmoid
// ---------------------------------------------------------------------------
__global__ __launch_bounds__(256) void out_kernel(
    const float* __restrict__ outW, const float* __restrict__ outB,
    float* __restrict__ out, int B)
{
    int warp = (blockIdx.x * blockDim.x + threadIdx.x) >> 5;
    int lane = threadIdx.x & 31;
    if (warp >= B) return;
    const float* h = g_h3 + (size_t)warp * D3;
    float s = 0.f;
#pragma unroll
    for (int j = 0; j < D3 / 32; j++)
        s += h[lane + 32 * j] * outW[lane + 32 * j];
#pragma unroll
    for (int o = 16; o; o >>= 1)
        s += __shfl_down_sync(0xffffffffu, s, o);
    if (lane == 0) {
        float x = s + outB[0] + g_li[warp];
        out[warp] = 1.f / (1.f + expf(-x));
    }
}

// ---------------------------------------------------------------------------
extern "C" void kernel_launch(void* const* d_in, const int* in_sizes, int n_in,
                              void* d_out, int out_size)
{
    const int*   feat_ids  = (const int*)  d_in[0];
    const float* feat_vals = (const float*)d_in[1];
    const float* FM_W      = (const float*)d_in[2];
    const float* FM_V      = (const float*)d_in[3];
    const float* FM_B      = (const float*)d_in[4];
    const float* emb       = (const float*)d_in[5];
    const float* W0        = (const float*)d_in[6];
    const float* B0        = (const float*)d_in[7];
    const float* W1        = (const float*)d_in[8];
    const float* B1        = (const float*)d_in[9];
    const float* W2        = (const float*)d_in[10];
    const float* B2        = (const float*)d_in[11];
    const float* outW      = (const float*)d_in[12];
    const float* outB      = (const float*)d_in[13];
    float* out = (float*)d_out;

    int B = in_sizes[0] / FIELD;
    if (B > MAXB) B = MAXB;

    float *h0, *h1, *h2, *h3;
    cudaGetSymbolAddress((void**)&h0, g_h0);
    cudaGetSymbolAddress((void**)&h1, g_h1);
    cudaGetSymbolAddress((void**)&h2, g_h2);
    cudaGetSymbolAddress((void**)&h3, g_h3);

    compute_S_kernel<<<1, 256>>>(FM_V);
    linear_inter_kernel<<<(B + 255) / 256, 256>>>(feat_ids, feat_vals, FM_W, FM_B, B);
    gather_kernel<<<(B * FIELD + 255) / 256, 256>>>(feat_ids, emb, B);

    gemm128_bias_relu<<<dim3(D1 / 128, B / 128), 256>>>(h0, W0, B0, h1, B, D1, D0);
    gemm128_bias_relu<<<dim3(D2 / 128, B / 128), 256>>>(h1, W1, B1, h2, B, D2, D1);
    gemm128_bias_relu<<<dim3(D3 / 128, B / 128), 256>>>(h2, W2, B2, h3, B, D3, D2);

    out_kernel<<<(B * 32 + 255) / 256, 256>>>(outW, outB, out, B);
}

// round 2
// speedup vs baseline: 1.0011x; 1.0011x over previous
#include <cuda_runtime.h>
#include <math.h>

#define FIELD 39
#define EMBD 8
#define MAXB 16384
#define D0 312
#define D1 512
#define D2 256
#define D3 128

// Scratch (allocation-free rule: __device__ globals)
__device__ float g_S[FIELD * FIELD];
__device__ float g_li[MAXB];
__device__ float g_h0[MAXB * D0];
__device__ float g_h1[MAXB * D1];
__device__ float g_h2[MAXB * D2];
__device__ float g_h3[MAXB * D3];

// ---------------------------------------------------------------------------
// 1. S matrix: constant 39x39, strictly upper triangular.
//    Vi[i][g][e] = FM_V[i, i*1000, g, e];  S[i][j] = sum_e Vi[i][j%8][e]*Vi[j][i%8][e]
// ---------------------------------------------------------------------------
__global__ void compute_S_kernel(const float* __restrict__ FM_V) {
    __shared__ float Vi[FIELD][8][EMBD];
    for (int idx = threadIdx.x; idx < FIELD * 64; idx += blockDim.x) {
        int i = idx / 64;
        int r = idx % 64;
        // offset = ((i*50000 + i*1000) * 8 + g) * 8 + e = i*51000*64 + r
        long long off = (long long)i * (51000LL * 64LL) + r;
        Vi[i][r >> 3][r & 7] = FM_V[off];
    }
    __syncthreads();
    for (int idx = threadIdx.x; idx < FIELD * FIELD; idx += blockDim.x) {
        int i = idx / FIELD, j = idx % FIELD;
        float s = 0.f;
        if (j > i) {
#pragma unroll
            for (int e = 0; e < EMBD; e++)
                s += Vi[i][j & 7][e] * Vi[j][i & 7][e];
        }
        g_S[idx] = s;
    }
}

// ---------------------------------------------------------------------------
// 2. linear + interaction per sample (one thread per sample)
// ---------------------------------------------------------------------------
__global__ __launch_bounds__(256) void linear_inter_kernel(
    const int* __restrict__ ids, const float* __restrict__ vals,
    const float* __restrict__ FM_W, const float* __restrict__ FM_B, int B)
{
    __shared__ float Ss[FIELD * FIELD];
    for (int idx = threadIdx.x; idx < FIELD * FIELD; idx += blockDim.x)
        Ss[idx] = g_S[idx];
    __syncthreads();

    int b = blockIdx.x * blockDim.x + threadIdx.x;
    if (b >= B) return;

    float v[FIELD];
    float lin = 0.f;
#pragma unroll
    for (int f = 0; f < FIELD; f++) {
        v[f] = vals[b * FIELD + f];
        lin += FM_W[ids[b * FIELD + f]] * v[f];
    }
    float inter = 0.f;
#pragma unroll
    for (int i = 0; i < FIELD; i++) {
        float ti = 0.f;
#pragma unroll
        for (int j = i + 1; j < FIELD; j++)
            ti += Ss[i * FIELD + j] * v[j];
        inter += v[i] * ti;
    }
    g_li[b] = lin + inter + FM_B[0];
}

// ---------------------------------------------------------------------------
// 3. embedding gather -> h0 (B x 312), thread per (b, field), float4 x2
// ---------------------------------------------------------------------------
__global__ void gather_kernel(const int* __restrict__ ids,
                              const float* __restrict__ emb, int B)
{
    int idx = blockIdx.x * blockDim.x + threadIdx.x;
    if (idx >= B * FIELD) return;
    int id = ids[idx];
    int b = idx / FIELD, f = idx % FIELD;
    const float4* e = (const float4*)(emb + (size_t)id * EMBD);
    float4* dst = (float4*)(g_h0 + (size_t)b * D0 + f * EMBD);
    float4 e0 = e[0];
    float4 e1 = e[1];
    dst[0] = e0;
    dst[1] = e1;
}

// ---------------------------------------------------------------------------
// 4. fp32 SGEMM + bias + ReLU.  C[M,N] = relu(A[M,K] @ W[K,N] + bias)
//    BM=BN=128, BK=8, 256 threads, 8x8 per-thread tile.
//    Requires M%128==0, N%128==0, K%8==0 (true for all layers).
// ---------------------------------------------------------------------------
__global__ __launch_bounds__(256) void gemm128_bias_relu(
    const float* __restrict__ A, const float* __restrict__ W,
    const float* __restrict__ bias, float* __restrict__ C,
    int M, int N, int K)
{
    __shared__ float As[8][128];
    __shared__ float Bs[8][128];

    const int t = threadIdx.x;
    const int bm = blockIdx.y * 128;
    const int bn = blockIdx.x * 128;
    const int tx = t & 15, ty = t >> 4;
    const int tm = ty * 8, tn = tx * 8;

    // load mappings (one float4 each per stage)
    const int arow = t >> 1, acol = (t & 1) * 4;   // A: 128 rows x 8 cols
    const int wrow = t >> 5, wcol = (t & 31) * 4;  // W: 8 rows x 128 cols

    float acc[8][8] = {};

    const float* Ap = A + (size_t)(bm + arow) * K + acol;
    for (int k0 = 0; k0 < K; k0 += 8) {
        float4 a = *(const float4*)(Ap + k0);
        As[acol + 0][arow] = a.x;
        As[acol + 1][arow] = a.y;
        As[acol + 2][arow] = a.z;
        As[acol + 3][arow] = a.w;
        float4 w = *(const float4*)(W + (size_t)(k0 + wrow) * N + bn + wcol);
        *(float4*)&Bs[wrow][wcol] = w;
        __syncthreads();

#pragma unroll
        for (int k = 0; k < 8; k++) {
            float ra[8], rb[8];
            *(float4*)&ra[0] = *(const float4*)&As[k][tm];
            *(float4*)&ra[4] = *(const float4*)&As[k][tm + 4];
            *(float4*)&rb[0] = *(const float4*)&Bs[k][tn];
            *(float4*)&rb[4] = *(const float4*)&Bs[k][tn + 4];
#pragma unroll
            for (int i = 0; i < 8; i++)
#pragma unroll
                for (int j = 0; j < 8; j++)
                    acc[i][j] += ra[i] * rb[j];
        }
        __syncthreads();
    }

    float bvals[8];
#pragma unroll
    for (int j = 0; j < 8; j++) bvals[j] = bias[bn + tn + j];

#pragma unroll
    for (int i = 0; i < 8; i++) {
        float* crow = C + (size_t)(bm + tm + i) * N + bn + tn;
#pragma unroll
        for (int j = 0; j < 8; j += 4) {
            float4 o;
            o.x = fmaxf(acc[i][j + 0] + bvals[j + 0], 0.f);
            o.y = fmaxf(acc[i][j + 1] + bvals[j + 1], 0.f);
            o.z = fmaxf(acc[i][j + 2] + bvals[j + 2], 0.f);
            o.w = fmaxf(acc[i][j + 3] + bvals[j + 3], 0.f);
            *(float4*)(crow + j) = o;
        }
    }
}

// ---------------------------------------------------------------------------
// 5. output head: warp per sample. dot(h3, outW) + outB + li -> sigmoid
// ---------------------------------------------------------------------------
__global__ __launch_bounds__(256) void out_kernel(
    const float* __restrict__ outW, const float* __restrict__ outB,
    float* __restrict__ out, int B)
{
    int warp = (blockIdx.x * blockDim.x + threadIdx.x) >> 5;
    int lane = threadIdx.x & 31;
    if (warp >= B) return;
    const float* h = g_h3 + (size_t)warp * D3;
    float s = 0.f;
#pragma unroll
    for (int j = 0; j < D3 / 32; j++)
        s += h[lane + 32 * j] * outW[lane + 32 * j];
#pragma unroll
    for (int o = 16; o; o >>= 1)
        s += __shfl_down_sync(0xffffffffu, s, o);
    if (lane == 0) {
        float x = s + outB[0] + g_li[warp];
        out[warp] = 1.f / (1.f + expf(-x));
    }
}

// ---------------------------------------------------------------------------
extern "C" void kernel_launch(void* const* d_in, const int* in_sizes, int n_in,
                              void* d_out, int out_size)
{
    const int*   feat_ids  = (const int*)  d_in[0];
    const float* feat_vals = (const float*)d_in[1];
    const float* FM_W      = (const float*)d_in[2];
    const float* FM_V      = (const float*)d_in[3];
    const float* FM_B      = (const float*)d_in[4];
    const float* emb       = (const float*)d_in[5];
    const float* W0        = (const float*)d_in[6];
    const float* B0        = (const float*)d_in[7];
    const float* W1        = (const float*)d_in[8];
    const float* B1        = (const float*)d_in[9];
    const float* W2        = (const float*)d_in[10];
    const float* B2        = (const float*)d_in[11];
    const float* outW      = (const float*)d_in[12];
    const float* outB      = (const float*)d_in[13];
    float* out = (float*)d_out;

    int B = in_sizes[0] / FIELD;
    if (B > MAXB) B = MAXB;

    float *h0, *h1, *h2, *h3;
    cudaGetSymbolAddress((void**)&h0, g_h0);
    cudaGetSymbolAddress((void**)&h1, g_h1);
    cudaGetSymbolAddress((void**)&h2, g_h2);
    cudaGetSymbolAddress((void**)&h3, g_h3);

    compute_S_kernel<<<1, 256>>>(FM_V);
    linear_inter_kernel<<<(B + 255) / 256, 256>>>(feat_ids, feat_vals, FM_W, FM_B, B);
    gather_kernel<<<(B * FIELD + 255) / 256, 256>>>(feat_ids, emb, B);

    gemm128_bias_relu<<<dim3(D1 / 128, B / 128), 256>>>(h0, W0, B0, h1, B, D1, D0);
    gemm128_bias_relu<<<dim3(D2 / 128, B / 128), 256>>>(h1, W1, B1, h2, B, D2, D1);
    gemm128_bias_relu<<<dim3(D3 / 128, B / 128), 256>>>(h2, W2, B2, h3, B, D3, D2);

    out_kernel<<<(B * 32 + 255) / 256, 256>>>(outW, outB, out, B);
}